// round 14
// baseline (speedup 1.0000x reference)
#include <cuda_runtime.h>
#include <cuda_fp16.h>
#include <cstdint>

#define M_TOT 4096
#define N_TOT 11008
#define K_TOT 4096
#define QWC   1376            // N_TOT/8 packed words per k-row

#define BM 128
#define BN 64
#define BK 64
#define NCH (K_TOT / BK)      // 64
#define THREADS 192           // 4 consumer warps + 2 producer warps
#define NSTAGE 4

// per-stage layout: A 16KB + B 8KB
#define STG_BYTES 24576
#define OFF_A 0
#define OFF_B 16384
// smem map
#define OFF_BAR 0
#define OFF_STG 1024
#define OFF_SC  (OFF_STG + NSTAGE * STG_BYTES)      // 99328 (fp16 scales, 4KB)
#define SMEM_TOTAL (OFF_SC + 4096)                  // 103424 -> 2 CTAs/SM

// fp16 bias: 0x6400 = 1024.0, ulp = 1 -> (0x6400|nib) == 1024 + nib exactly
#define BIAS2 0x64006400u

// prepass scratch: A as fp16, [M][K] row-major
__device__ __half AhG[(size_t)M_TOT * K_TOT];

__device__ __forceinline__ uint32_t smem_u32(const void* p) {
    uint32_t a;
    asm("{ .reg .u64 t; cvta.to.shared.u64 t, %1; cvt.u32.u64 %0, t; }"
        : "=r"(a) : "l"(p));
    return a;
}
__device__ __forceinline__ void ldsm4(uint32_t* r, uint32_t addr) {
    asm volatile("ldmatrix.sync.aligned.m8n8.x4.shared.b16 {%0,%1,%2,%3}, [%4];"
                 : "=r"(r[0]), "=r"(r[1]), "=r"(r[2]), "=r"(r[3]) : "r"(addr));
}
__device__ __forceinline__ void ldsm4t(uint32_t* r, uint32_t addr) {
    asm volatile("ldmatrix.sync.aligned.m8n8.x4.trans.shared.b16 {%0,%1,%2,%3}, [%4];"
                 : "=r"(r[0]), "=r"(r[1]), "=r"(r[2]), "=r"(r[3]) : "r"(addr));
}
__device__ __forceinline__ void mma_f16(float* d, const uint32_t* a, const uint32_t* b) {
    asm volatile(
        "mma.sync.aligned.m16n8k16.row.col.f32.f16.f16.f32 "
        "{%0,%1,%2,%3}, {%4,%5,%6,%7}, {%8,%9}, {%0,%1,%2,%3};"
        : "+f"(d[0]), "+f"(d[1]), "+f"(d[2]), "+f"(d[3])
        : "r"(a[0]), "r"(a[1]), "r"(a[2]), "r"(a[3]), "r"(b[0]), "r"(b[1]));
}
__device__ __forceinline__ void mbar_init(uint32_t m, uint32_t c) {
    asm volatile("mbarrier.init.shared.b64 [%0], %1;" :: "r"(m), "r"(c) : "memory");
}
__device__ __forceinline__ void mbar_arrive(uint32_t m) {
    asm volatile("mbarrier.arrive.shared.b64 _, [%0];" :: "r"(m) : "memory");
}
__device__ __forceinline__ void mbar_wait(uint32_t m, uint32_t parity) {
    uint32_t done;
    asm volatile(
        "{\n\t.reg .pred p;\n\t"
        "mbarrier.try_wait.parity.acquire.cta.shared::cta.b64 p, [%1], %2;\n\t"
        "selp.b32 %0, 1, 0, p;\n\t}"
        : "=r"(done) : "r"(m), "r"(parity) : "memory");
    if (!done) {
        asm volatile(
            "{\n\t.reg .pred P1;\n\t"
            "WL_%=:\n\t"
            "mbarrier.try_wait.parity.acquire.cta.shared::cta.b64 P1, [%0], %1, 0x989680;\n\t"
            "@P1 bra.uni WD_%=;\n\t"
            "bra.uni WL_%=;\n\t"
            "WD_%=:\n\t}"
            :: "r"(m), "r"(parity) : "memory");
    }
}
__device__ __forceinline__ void cp_async16(uint32_t dst, const void* src) {
    asm volatile("cp.async.cg.shared.global [%0], [%1], 16;"
                 :: "r"(dst), "l"(src) : "memory");
}

// ============ A prepass: fp32 -> fp16 ============
__global__ void __launch_bounds__(256) cvtA_kernel(const float* __restrict__ A) {
    const size_t base = ((size_t)blockIdx.x * 256 + threadIdx.x) * 8;
    const float4 v0 = *reinterpret_cast<const float4*>(A + base);
    const float4 v1 = *reinterpret_cast<const float4*>(A + base + 4);
    __half2 h0 = __floats2half2_rn(v0.x, v0.y);
    __half2 h1 = __floats2half2_rn(v0.z, v0.w);
    __half2 h2 = __floats2half2_rn(v1.x, v1.y);
    __half2 h3 = __floats2half2_rn(v1.z, v1.w);
    *reinterpret_cast<uint4*>(AhG + base) =
        make_uint4(*(uint32_t*)&h0, *(uint32_t*)&h1, *(uint32_t*)&h2, *(uint32_t*)&h3);
}

// ============ warp-specialized fused GEMM, 2 CTAs/SM ============
__global__ void __launch_bounds__(THREADS, 2) gemm_f16_kernel(
    const unsigned* __restrict__ QW, const unsigned* __restrict__ QZ,
    const float* __restrict__ SC, float* __restrict__ C)
{
    extern __shared__ char smem[];
    const uint32_t sbase = smem_u32(smem);
    const int tid  = threadIdx.x;
    const int wid  = tid >> 5;
    const int lane = tid & 31;
    const int bm = blockIdx.y * BM;
    const int bn = blockIdx.x * BN;
    __half* scS = (__half*)(smem + OFF_SC);

    if (tid == 0) {
        #pragma unroll
        for (int s = 0; s < NSTAGE; s++) {
            mbar_init(sbase + OFF_BAR + 16 * s, 64);       // full: producer threads
            mbar_init(sbase + OFF_BAR + 16 * s + 8, 128);  // empty: consumer threads
        }
    }
    // stage scales as fp16 (32 groups x 64 n)
    for (int idx = tid; idx < 512; idx += THREADS) {
        const int g = idx >> 4, v = idx & 15;
        const float4 s4 = *reinterpret_cast<const float4*>(
            SC + (size_t)g * N_TOT + bn + v * 4);
        __half2 a = __floats2half2_rn(s4.x, s4.y);
        __half2 b = __floats2half2_rn(s4.z, s4.w);
        *reinterpret_cast<uint2*>(scS + g * 64 + v * 4) =
            make_uint2(*(uint32_t*)&a, *(uint32_t*)&b);
    }
    __syncthreads();

    if (wid >= 4) {
        // ========== PRODUCER (warps 4-5, 64 threads) ==========
        const int ptid = tid - 128;
        const int bw  = ptid & 7;      // B n-octet / packed-word (0..7)
        const int bkb = ptid >> 3;     // B k base 0..7 (+8*r)
        int pe[NSTAGE] = {1, 1, 1, 1};

        for (int it = 0; it < NCH; ++it) {
            const int s = it % NSTAGE;
            mbar_wait(sbase + OFF_BAR + 16 * s + 8, pe[s]);
            pe[s] ^= 1;
            const int k0 = it * BK;
            char* stg = smem + OFF_STG + s * STG_BYTES;
            const uint32_t stgu = sbase + OFF_STG + s * STG_BYTES;

            // ---- A: cp.async fp16 straight into swizzled slots ----
            #pragma unroll
            for (int r = 0; r < 16; r++) {
                const int idx = ptid + r * 64;      // 0..1023
                const int m = idx >> 3, c = idx & 7;
                const __half* src = AhG + (size_t)(bm + m) * K_TOT + k0 + c * 8;
                const uint32_t dst = stgu + OFF_A + m * 128 + ((c ^ (m & 7)) << 4);
                cp_async16(dst, src);
            }
            asm volatile("cp.async.commit_group;" ::: "memory");

            // ---- B: q = nib - zp exact (bias 0x6400), then * s_fp16 ----
            const unsigned qz = QZ[(size_t)(it >> 1) * QWC + (bn >> 3) + bw];
            unsigned qw[8];
            #pragma unroll
            for (int r = 0; r < 8; r++)
                qw[r] = QW[(size_t)(k0 + bkb + 8 * r) * QWC + (bn >> 3) + bw];
            uint32_t zz[4];
            #pragma unroll
            for (int p = 0; p < 4; p++) {
                const unsigned zq = qz >> (8 * p);
                zz[p] = BIAS2 | (zq & 0xFu) | ((zq & 0xF0u) << 12);
            }
            uint4 sv = *reinterpret_cast<const uint4*>(
                scS + (size_t)(it >> 1) * 64 + bw * 8);
            const uint32_t sc2[4] = {sv.x, sv.y, sv.z, sv.w};
            #pragma unroll
            for (int r = 0; r < 8; r++) {
                const int k = bkb + 8 * r;
                const unsigned q = qw[r];
                uint32_t w[4];
                #pragma unroll
                for (int p = 0; p < 4; p++) {
                    const unsigned qq = q >> (8 * p);
                    uint32_t u = BIAS2 | (qq & 0xFu) | ((qq & 0xF0u) << 12);
                    __half2 d = __hsub2(*reinterpret_cast<__half2*>(&u),
                                        *reinterpret_cast<__half2*>(&zz[p]));
                    __half2 b = __hmul2(d, *reinterpret_cast<const __half2*>(&sc2[p]));
                    w[p] = *reinterpret_cast<uint32_t*>(&b);
                }
                const int off = k * 128 + ((bw ^ (k & 7)) << 4);
                *reinterpret_cast<uint4*>(stg + OFF_B + off) =
                    make_uint4(w[0], w[1], w[2], w[3]);
            }
            asm volatile("cp.async.wait_group 0;" ::: "memory");
            mbar_arrive(sbase + OFF_BAR + 16 * s);   // full
        }
    } else {
        // ========== CONSUMER (warps 0-3, 128 threads), 64x32 warp tiles ==========
        const int wm = (wid & 1) * 64;
        const int wn = (wid >> 1) * 32;
        const int rsel = ((lane >> 3) & 1) * 8 + (lane & 7);
        const int hi8  = lane >> 4;
        const int l7   = lane & 7;
        int cf[NSTAGE] = {0, 0, 0, 0};

        float accF[4][4][4];
        #pragma unroll
        for (int i = 0; i < 4; i++)
            #pragma unroll
            for (int j = 0; j < 4; j++)
                #pragma unroll
                for (int e = 0; e < 4; e++) accF[i][j][e] = 0.f;

        for (int it = 0; it < NCH; ++it) {
            const int s = it % NSTAGE;
            mbar_wait(sbase + OFF_BAR + 16 * s, cf[s]);
            cf[s] ^= 1;

            const uint32_t base = sbase + OFF_STG + s * STG_BYTES;
            #pragma unroll
            for (int ks = 0; ks < 4; ks++) {
                uint32_t bq[4][2];
                const int krow = ks * 16 + rsel;
                #pragma unroll
                for (int pr = 0; pr < 2; pr++) {
                    const int ch = (wn >> 3) + pr * 2 + hi8;
                    const int off = krow * 128 + ((ch ^ l7) << 4);
                    uint32_t t[4];
                    ldsm4t(t, base + OFF_B + off);
                    bq[pr*2][0]=t[0]; bq[pr*2][1]=t[1];
                    bq[pr*2+1][0]=t[2]; bq[pr*2+1][1]=t[3];
                }
                #pragma unroll
                for (int mi = 0; mi < 4; mi++) {
                    const int m = wm + mi * 16 + rsel;
                    const int aoff = m * 128 + (((ks * 2 + hi8) ^ l7) << 4);
                    uint32_t a[4];
                    ldsm4(a, base + OFF_A + aoff);
                    #pragma unroll
                    for (int nj = 0; nj < 4; nj++) mma_f16(accF[mi][nj], a, bq[nj]);
                }
            }
            mbar_arrive(sbase + OFF_BAR + 16 * s + 8);   // empty
        }

        // epilogue
        #pragma unroll
        for (int mi = 0; mi < 4; mi++)
            #pragma unroll
            for (int nj = 0; nj < 4; nj++) {
                const float* a = accF[mi][nj];
                const int row = bm + wm + mi * 16 + (lane >> 2);
                const int col = bn + wn + nj * 8 + (lane & 3) * 2;
                *reinterpret_cast<float2*>(&C[(size_t)row * N_TOT + col]) =
                    make_float2(a[0], a[1]);
                *reinterpret_cast<float2*>(&C[(size_t)(row + 8) * N_TOT + col]) =
                    make_float2(a[2], a[3]);
            }
    }
}

extern "C" void kernel_launch(void* const* d_in, const int* in_sizes, int n_in,
                              void* d_out, int out_size)
{
    const float*    A  = (const float*)d_in[0];
    const unsigned* QW = (const unsigned*)d_in[1];
    const unsigned* QZ = (const unsigned*)d_in[2];
    const float*    SC = (const float*)d_in[3];
    float*          C  = (float*)d_out;

    cvtA_kernel<<<(M_TOT * K_TOT) / (256 * 8), 256>>>(A);

    cudaFuncSetAttribute(gemm_f16_kernel,
                         cudaFuncAttributeMaxDynamicSharedMemorySize, SMEM_TOTAL);
    dim3 grid(N_TOT / BN, M_TOT / BM);   // (172, 32)
    gemm_f16_kernel<<<grid, THREADS, SMEM_TOTAL>>>(QW, QZ, SC, C);
}

// round 15
// speedup vs baseline: 1.1520x; 1.1520x over previous
#include <cuda_runtime.h>
#include <cuda_fp16.h>
#include <cstdint>

#define M_TOT 4096
#define N_TOT 11008
#define K_TOT 4096
#define QWC   1376            // N_TOT/8 packed words per k-row

#define BM 128
#define BN 128
#define BK 64
#define NCH (K_TOT / BK)      // 64
#define THREADS 256           // 4 consumer warps + 4 producer warps
#define NSTAGE 5

// per-stage layout: A 16KB + B 16KB
#define STG_BYTES 32768
#define OFF_A 0
#define OFF_B 16384
// smem map
#define OFF_BAR 0
#define OFF_STG 1024
#define OFF_SC  (OFF_STG + NSTAGE * STG_BYTES)      // 164864 (fp16 scales, 8KB)
#define SMEM_TOTAL (OFF_SC + 8192)                  // 173056

// fp16 bias: 0x6400 = 1024.0, ulp = 1 -> (0x6400|nib) == 1024 + nib exactly
#define BIAS2 0x64006400u

// prepass scratch: A as fp16, [M][K] row-major
__device__ __half AhG[(size_t)M_TOT * K_TOT];

__device__ __forceinline__ uint32_t smem_u32(const void* p) {
    uint32_t a;
    asm("{ .reg .u64 t; cvta.to.shared.u64 t, %1; cvt.u32.u64 %0, t; }"
        : "=r"(a) : "l"(p));
    return a;
}
__device__ __forceinline__ void ldsm4(uint32_t* r, uint32_t addr) {
    asm volatile("ldmatrix.sync.aligned.m8n8.x4.shared.b16 {%0,%1,%2,%3}, [%4];"
                 : "=r"(r[0]), "=r"(r[1]), "=r"(r[2]), "=r"(r[3]) : "r"(addr));
}
__device__ __forceinline__ void ldsm4t(uint32_t* r, uint32_t addr) {
    asm volatile("ldmatrix.sync.aligned.m8n8.x4.trans.shared.b16 {%0,%1,%2,%3}, [%4];"
                 : "=r"(r[0]), "=r"(r[1]), "=r"(r[2]), "=r"(r[3]) : "r"(addr));
}
__device__ __forceinline__ void mma_f16(float* d, const uint32_t* a, const uint32_t* b) {
    asm volatile(
        "mma.sync.aligned.m16n8k16.row.col.f32.f16.f16.f32 "
        "{%0,%1,%2,%3}, {%4,%5,%6,%7}, {%8,%9}, {%0,%1,%2,%3};"
        : "+f"(d[0]), "+f"(d[1]), "+f"(d[2]), "+f"(d[3])
        : "r"(a[0]), "r"(a[1]), "r"(a[2]), "r"(a[3]), "r"(b[0]), "r"(b[1]));
}
__device__ __forceinline__ void mbar_init(uint32_t m, uint32_t c) {
    asm volatile("mbarrier.init.shared.b64 [%0], %1;" :: "r"(m), "r"(c) : "memory");
}
__device__ __forceinline__ void mbar_arrive(uint32_t m) {
    asm volatile("mbarrier.arrive.shared.b64 _, [%0];" :: "r"(m) : "memory");
}
__device__ __forceinline__ void mbar_wait(uint32_t m, uint32_t parity) {
    uint32_t done;
    asm volatile(
        "{\n\t.reg .pred p;\n\t"
        "mbarrier.try_wait.parity.acquire.cta.shared::cta.b64 p, [%1], %2;\n\t"
        "selp.b32 %0, 1, 0, p;\n\t}"
        : "=r"(done) : "r"(m), "r"(parity) : "memory");
    if (!done) {
        asm volatile(
            "{\n\t.reg .pred P1;\n\t"
            "WL_%=:\n\t"
            "mbarrier.try_wait.parity.acquire.cta.shared::cta.b64 P1, [%0], %1, 0x989680;\n\t"
            "@P1 bra.uni WD_%=;\n\t"
            "bra.uni WL_%=;\n\t"
            "WD_%=:\n\t}"
            :: "r"(m), "r"(parity) : "memory");
    }
}
__device__ __forceinline__ void cp_async16(uint32_t dst, const void* src) {
    asm volatile("cp.async.cg.shared.global [%0], [%1], 16;"
                 :: "r"(dst), "l"(src) : "memory");
}

// ============ A prepass: fp32 -> fp16 ============
__global__ void __launch_bounds__(256) cvtA_kernel(const float* __restrict__ A) {
    const size_t base = ((size_t)blockIdx.x * 256 + threadIdx.x) * 8;
    const float4 v0 = *reinterpret_cast<const float4*>(A + base);
    const float4 v1 = *reinterpret_cast<const float4*>(A + base + 4);
    __half2 h0 = __floats2half2_rn(v0.x, v0.y);
    __half2 h1 = __floats2half2_rn(v0.z, v0.w);
    __half2 h2 = __floats2half2_rn(v1.x, v1.y);
    __half2 h3 = __floats2half2_rn(v1.z, v1.w);
    *reinterpret_cast<uint4*>(AhG + base) =
        make_uint4(*(uint32_t*)&h0, *(uint32_t*)&h1, *(uint32_t*)&h2, *(uint32_t*)&h3);
}

// ============ warp-specialized fused GEMM ============
__global__ void __launch_bounds__(THREADS, 1) gemm_f16_kernel(
    const unsigned* __restrict__ QW, const unsigned* __restrict__ QZ,
    const float* __restrict__ SC, float* __restrict__ C)
{
    extern __shared__ char smem[];
    const uint32_t sbase = smem_u32(smem);
    const int tid  = threadIdx.x;
    const int wid  = tid >> 5;
    const int lane = tid & 31;
    const int bm = blockIdx.y * BM;
    const int bn = blockIdx.x * BN;
    __half* scS = (__half*)(smem + OFF_SC);

    if (tid == 0) {
        #pragma unroll
        for (int s = 0; s < NSTAGE; s++) {
            mbar_init(sbase + OFF_BAR + 16 * s, 128);      // full: producer threads
            mbar_init(sbase + OFF_BAR + 16 * s + 8, 128);  // empty: consumer threads
        }
    }
    // stage scales as fp16 (32 groups x 128 n)
    for (int idx = tid; idx < 1024; idx += THREADS) {
        const int g = idx >> 5, v = idx & 31;
        const float4 s4 = *reinterpret_cast<const float4*>(
            SC + (size_t)g * N_TOT + bn + v * 4);
        __half2 a = __floats2half2_rn(s4.x, s4.y);
        __half2 b = __floats2half2_rn(s4.z, s4.w);
        *reinterpret_cast<uint2*>(scS + g * 128 + v * 4) =
            make_uint2(*(uint32_t*)&a, *(uint32_t*)&b);
    }
    __syncthreads();

    if (wid >= 4) {
        // ========== PRODUCER (warps 4-7, 128 threads) ==========
        const int ptid = tid - 128;
        const int bw  = ptid & 15;     // B n-octet / packed-word
        const int bkb = ptid >> 4;     // B k base 0..7 (+8*r)
        int pe[NSTAGE] = {1, 1, 1, 1, 1};

        unsigned qwA[8], qwB[8], qzA, qzB;
        uint4 svA, svB;

        // issue global loads for a chunk into a register set (no smem touched)
        #define PLOADS(chunk, qwR, qzR, svR)                                       \
            {                                                                      \
                const int _k0 = (chunk) * BK;                                      \
                qzR = QZ[(size_t)((chunk) >> 1) * QWC + (bn >> 3) + bw];           \
                _Pragma("unroll")                                                  \
                for (int r = 0; r < 8; r++)                                        \
                    qwR[r] = QW[(size_t)(_k0 + bkb + 8 * r) * QWC + (bn >> 3) + bw]; \
                svR = *reinterpret_cast<const uint4*>(                             \
                    scS + (size_t)((chunk) >> 1) * 128 + bw * 8);                  \
            }

        // consume a register set: wait empty, cp.async A(it), dequant+STS B(it),
        // then drain A(it-1)'s group and arrive full[it-1]  (deferred handoff)
        #define PBODY(it, qwR, qzR, svR)                                           \
            {                                                                      \
                const int s = (it) % NSTAGE;                                       \
                mbar_wait(sbase + OFF_BAR + 16 * s + 8, pe[s]);                    \
                pe[s] ^= 1;                                                        \
                const int k0 = (it) * BK;                                          \
                char* stg = smem + OFF_STG + s * STG_BYTES;                        \
                const uint32_t stgu = sbase + OFF_STG + s * STG_BYTES;             \
                _Pragma("unroll")                                                  \
                for (int r = 0; r < 8; r++) {                                      \
                    const int idx = ptid + r * 128;                                \
                    const int m = idx >> 3, c = idx & 7;                           \
                    const __half* src = AhG + (size_t)(bm + m) * K_TOT + k0 + c * 8; \
                    const uint32_t dst = stgu + OFF_A + m * 128 + ((c ^ (m & 7)) << 4); \
                    cp_async16(dst, src);                                          \
                }                                                                  \
                asm volatile("cp.async.commit_group;" ::: "memory");               \
                uint32_t zz[4];                                                    \
                _Pragma("unroll")                                                  \
                for (int p = 0; p < 4; p++) {                                      \
                    const unsigned zq = qzR >> (8 * p);                            \
                    zz[p] = BIAS2 | (zq & 0xFu) | ((zq & 0xF0u) << 12);            \
                }                                                                  \
                const uint32_t sc2[4] = {svR.x, svR.y, svR.z, svR.w};              \
                _Pragma("unroll")                                                  \
                for (int r = 0; r < 8; r++) {                                      \
                    const int k = bkb + 8 * r;                                     \
                    const unsigned q = qwR[r];                                     \
                    uint32_t w[4];                                                 \
                    _Pragma("unroll")                                              \
                    for (int p = 0; p < 4; p++) {                                  \
                        const unsigned qq = q >> (8 * p);                          \
                        uint32_t u = BIAS2 | (qq & 0xFu) | ((qq & 0xF0u) << 12);   \
                        __half2 d = __hsub2(*reinterpret_cast<__half2*>(&u),       \
                                            *reinterpret_cast<__half2*>(&zz[p]));  \
                        __half2 b = __hmul2(d, *reinterpret_cast<const __half2*>(&sc2[p])); \
                        w[p] = *reinterpret_cast<uint32_t*>(&b);                   \
                    }                                                              \
                    const int off = k * 256 + ((bw ^ (k & 7)) << 4);               \
                    *reinterpret_cast<uint4*>(stg + OFF_B + off) =                 \
                        make_uint4(w[0], w[1], w[2], w[3]);                        \
                }                                                                  \
                if ((it) > 0) {                                                    \
                    asm volatile("cp.async.wait_group 1;" ::: "memory");           \
                    mbar_arrive(sbase + OFF_BAR + 16 * (((it) - 1) % NSTAGE));     \
                }                                                                  \
            }

        PLOADS(0, qwA, qzA, svA);
        for (int it = 0; it < NCH; it += 2) {
            PLOADS(it + 1, qwB, qzB, svB);
            PBODY(it, qwA, qzA, svA);
            if (it + 2 < NCH) PLOADS(it + 2, qwA, qzA, svA);
            PBODY(it + 1, qwB, qzB, svB);
        }
        // tail: drain last A group, hand over final chunk
        asm volatile("cp.async.wait_group 0;" ::: "memory");
        mbar_arrive(sbase + OFF_BAR + 16 * ((NCH - 1) % NSTAGE));
    } else {
        // ========== CONSUMER (warps 0-3, 128 threads), 64x64 warp tiles ==========
        const int wm = (wid & 1) * 64;
        const int wn = (wid >> 1) * 64;
        const int rsel = ((lane >> 3) & 1) * 8 + (lane & 7);
        const int hi8  = lane >> 4;
        const int l7   = lane & 7;
        int cf[NSTAGE] = {0, 0, 0, 0, 0};

        float accF[4][8][4];
        #pragma unroll
        for (int i = 0; i < 4; i++)
            #pragma unroll
            for (int j = 0; j < 8; j++)
                #pragma unroll
                for (int e = 0; e < 4; e++) accF[i][j][e] = 0.f;

        for (int it = 0; it < NCH; ++it) {
            const int s = it % NSTAGE;
            mbar_wait(sbase + OFF_BAR + 16 * s, cf[s]);
            cf[s] ^= 1;

            const uint32_t base = sbase + OFF_STG + s * STG_BYTES;
            #pragma unroll
            for (int ks = 0; ks < 4; ks++) {
                uint32_t bq[8][2];
                const int krow = ks * 16 + rsel;
                #pragma unroll
                for (int pr = 0; pr < 4; pr++) {
                    const int ch = (wn >> 3) + pr * 2 + hi8;
                    const int off = krow * 256 + ((ch ^ l7) << 4);
                    uint32_t t[4];
                    ldsm4t(t, base + OFF_B + off);
                    bq[pr*2][0]=t[0]; bq[pr*2][1]=t[1];
                    bq[pr*2+1][0]=t[2]; bq[pr*2+1][1]=t[3];
                }
                #pragma unroll
                for (int mi = 0; mi < 4; mi++) {
                    const int m = wm + mi * 16 + rsel;
                    const int aoff = m * 128 + (((ks * 2 + hi8) ^ l7) << 4);
                    uint32_t a[4];
                    ldsm4(a, base + OFF_A + aoff);
                    #pragma unroll
                    for (int nj = 0; nj < 8; nj++) mma_f16(accF[mi][nj], a, bq[nj]);
                }
            }
            mbar_arrive(sbase + OFF_BAR + 16 * s + 8);   // empty
        }

        // epilogue
        #pragma unroll
        for (int mi = 0; mi < 4; mi++)
            #pragma unroll
            for (int nj = 0; nj < 8; nj++) {
                const float* a = accF[mi][nj];
                const int row = bm + wm + mi * 16 + (lane >> 2);
                const int col = bn + wn + nj * 8 + (lane & 3) * 2;
                *reinterpret_cast<float2*>(&C[(size_t)row * N_TOT + col]) =
                    make_float2(a[0], a[1]);
                *reinterpret_cast<float2*>(&C[(size_t)(row + 8) * N_TOT + col]) =
                    make_float2(a[2], a[3]);
            }
    }
}

extern "C" void kernel_launch(void* const* d_in, const int* in_sizes, int n_in,
                              void* d_out, int out_size)
{
    const float*    A  = (const float*)d_in[0];
    const unsigned* QW = (const unsigned*)d_in[1];
    const unsigned* QZ = (const unsigned*)d_in[2];
    const float*    SC = (const float*)d_in[3];
    float*          C  = (float*)d_out;

    cvtA_kernel<<<(M_TOT * K_TOT) / (256 * 8), 256>>>(A);

    cudaFuncSetAttribute(gemm_f16_kernel,
                         cudaFuncAttributeMaxDynamicSharedMemorySize, SMEM_TOTAL);
    dim3 grid(N_TOT / BN, M_TOT / BM);   // (86, 32)
    gemm_f16_kernel<<<grid, THREADS, SMEM_TOTAL>>>(QW, QZ, SC, C);
}